// round 1
// baseline (speedup 1.0000x reference)
#include <cuda_runtime.h>

// SpectralAttention: B=1024, S=3, A=256, D=256
//   s_in[b,a]    = dot(input[b,a,:],       w[:256])
//   s_sc[b,s,a]  = dot(scattered[b,s,a,:], w[256:])
//   scores = prelu(s_in + s_sc); out = softmax over s (axis=1), layout (B,S,A)
//
// One warp per (b,a). Each warp streams 4 contiguous 1KB rows via coalesced
// float4 loads, butterfly-reduces 4 dot products, then does the 3-way softmax
// in registers. Pure HBM-bound: 1.07 GB reads, ~155us floor at ~7 TB/s.

#define BB 1024
#define SS 3
#define AA 256
#define DD 256

__global__ __launch_bounds__(256, 8)
void spectral_attention_kernel(const float* __restrict__ input,
                               const float* __restrict__ scattered,
                               const float* __restrict__ weight,
                               const float* __restrict__ prelu,
                               float* __restrict__ out)
{
    const int lane = threadIdx.x & 31;
    const int warp = (blockIdx.x * blockDim.x + threadIdx.x) >> 5;  // 0 .. B*A-1
    const int b = warp >> 8;    // / AA
    const int a = warp & 255;   // % AA

    // Weights: 512 floats = 128 float4. w1 = vec[0..63], w2 = vec[64..127].
    const float4* __restrict__ wv = reinterpret_cast<const float4*>(weight);
    const float4 w1a = __ldg(&wv[lane]);
    const float4 w1b = __ldg(&wv[lane + 32]);
    const float4 w2a = __ldg(&wv[64 + lane]);
    const float4 w2b = __ldg(&wv[64 + lane + 32]);

    // input row: (b*A + a)*D floats, 64 float4s. Lane reads vec idx lane and lane+32
    // -> two fully coalesced 512B warp transactions per row.
    const float4* __restrict__ xr =
        reinterpret_cast<const float4*>(input + (((size_t)b * AA + a) * DD));
    const float4 x0 = __ldg(&xr[lane]);
    const float4 x1 = __ldg(&xr[lane + 32]);
    float p_in = x0.x * w1a.x + x0.y * w1a.y + x0.z * w1a.z + x0.w * w1a.w
               + x1.x * w1b.x + x1.y * w1b.y + x1.z * w1b.z + x1.w * w1b.w;

    float p_sc[SS];
#pragma unroll
    for (int s = 0; s < SS; ++s) {
        const float4* __restrict__ yr = reinterpret_cast<const float4*>(
            scattered + ((((size_t)b * SS + s) * AA + a) * (size_t)DD));
        const float4 y0 = __ldg(&yr[lane]);
        const float4 y1 = __ldg(&yr[lane + 32]);
        p_sc[s] = y0.x * w2a.x + y0.y * w2a.y + y0.z * w2a.z + y0.w * w2a.w
                + y1.x * w2b.x + y1.y * w2b.y + y1.z * w2b.z + y1.w * w2b.w;
    }

    // Butterfly reduce all 4 partial dots (every lane ends with the full sums).
#pragma unroll
    for (int off = 16; off > 0; off >>= 1) {
        p_in += __shfl_xor_sync(0xffffffffu, p_in, off);
#pragma unroll
        for (int s = 0; s < SS; ++s)
            p_sc[s] += __shfl_xor_sync(0xffffffffu, p_sc[s], off);
    }

    const float alpha = __ldg(prelu);
    float sc0 = p_in + p_sc[0];
    float sc1 = p_in + p_sc[1];
    float sc2 = p_in + p_sc[2];
    sc0 = sc0 >= 0.f ? sc0 : alpha * sc0;
    sc1 = sc1 >= 0.f ? sc1 : alpha * sc1;
    sc2 = sc2 >= 0.f ? sc2 : alpha * sc2;

    const float m = fmaxf(sc0, fmaxf(sc1, sc2));
    const float e0 = __expf(sc0 - m);
    const float e1 = __expf(sc1 - m);
    const float e2 = __expf(sc2 - m);
    const float inv = 1.0f / (e0 + e1 + e2);

    if (lane < SS) {
        const float e = (lane == 0) ? e0 : (lane == 1 ? e1 : e2);
        out[((size_t)b * SS + lane) * AA + a] = e * inv;
    }
}

extern "C" void kernel_launch(void* const* d_in, const int* in_sizes, int n_in,
                              void* d_out, int out_size)
{
    const float* input     = (const float*)d_in[0];  // (B, A, D) f32
    const float* scattered = (const float*)d_in[1];  // (B, S, A, D) f32
    const float* weight    = (const float*)d_in[2];  // (2D,) f32
    const float* prelu     = (const float*)d_in[3];  // (1,) f32
    float* out = (float*)d_out;                      // (B, S, A) f32

    const int total_warps = BB * AA;                 // 262144
    const int threads = 256;                         // 8 warps / block
    const int blocks = total_warps / (threads / 32); // 32768
    spectral_attention_kernel<<<blocks, threads>>>(input, scattered, weight, prelu, out);
}

// round 2
// speedup vs baseline: 1.0217x; 1.0217x over previous
#include <cuda_runtime.h>

// SpectralAttention: B=1024, S=3, A=256, D=256
// Pure HBM-bound streaming reduction (1.07 GB reads, ~134us floor @ 8 TB/s).
// R2: front-batched LDG.128 stream (MLP_p1=8 per warp), __ldcs streaming hints,
// relaxed reg budget so ptxas keeps all 8 loads in flight.

#define BB 1024
#define SS 3
#define AA 256
#define DD 256

__global__ __launch_bounds__(256, 4)
void spectral_attention_kernel(const float* __restrict__ input,
                               const float* __restrict__ scattered,
                               const float* __restrict__ weight,
                               const float* __restrict__ prelu,
                               float* __restrict__ out)
{
    const int lane = threadIdx.x & 31;
    const int warp = (blockIdx.x * blockDim.x + threadIdx.x) >> 5;  // 0 .. B*A-1
    const int b = warp >> 8;    // / AA
    const int a = warp & 255;   // % AA

    // ---- Front-batch ALL stream loads (8x LDG.128, evict-first) ----
    const float4* __restrict__ xr =
        reinterpret_cast<const float4*>(input + (((size_t)b * AA + a) * DD));
    const float4* __restrict__ y0r = reinterpret_cast<const float4*>(
        scattered + ((((size_t)b * SS + 0) * AA + a) * (size_t)DD));
    const float4* __restrict__ y1r = reinterpret_cast<const float4*>(
        scattered + ((((size_t)b * SS + 1) * AA + a) * (size_t)DD));
    const float4* __restrict__ y2r = reinterpret_cast<const float4*>(
        scattered + ((((size_t)b * SS + 2) * AA + a) * (size_t)DD));

    const float4 x0  = __ldcs(&xr[lane]);
    const float4 x1  = __ldcs(&xr[lane + 32]);
    const float4 ya0 = __ldcs(&y0r[lane]);
    const float4 ya1 = __ldcs(&y0r[lane + 32]);
    const float4 yb0 = __ldcs(&y1r[lane]);
    const float4 yb1 = __ldcs(&y1r[lane + 32]);
    const float4 yc0 = __ldcs(&y2r[lane]);
    const float4 yc1 = __ldcs(&y2r[lane + 32]);

    // ---- Weights (512 floats = 128 float4): L1/L2-resident after first wave ----
    const float4* __restrict__ wv = reinterpret_cast<const float4*>(weight);
    const float4 w1a = __ldg(&wv[lane]);
    const float4 w1b = __ldg(&wv[lane + 32]);
    const float4 w2a = __ldg(&wv[64 + lane]);
    const float4 w2b = __ldg(&wv[64 + lane + 32]);

    float p_in = x0.x * w1a.x + x0.y * w1a.y + x0.z * w1a.z + x0.w * w1a.w
               + x1.x * w1b.x + x1.y * w1b.y + x1.z * w1b.z + x1.w * w1b.w;
    float p0 = ya0.x * w2a.x + ya0.y * w2a.y + ya0.z * w2a.z + ya0.w * w2a.w
             + ya1.x * w2b.x + ya1.y * w2b.y + ya1.z * w2b.z + ya1.w * w2b.w;
    float p1 = yb0.x * w2a.x + yb0.y * w2a.y + yb0.z * w2a.z + yb0.w * w2a.w
             + yb1.x * w2b.x + yb1.y * w2b.y + yb1.z * w2b.z + yb1.w * w2b.w;
    float p2 = yc0.x * w2a.x + yc0.y * w2a.y + yc0.z * w2a.z + yc0.w * w2a.w
             + yc1.x * w2b.x + yc1.y * w2b.y + yc1.z * w2b.z + yc1.w * w2b.w;

    // Butterfly reduce all 4 partial dots.
#pragma unroll
    for (int off = 16; off > 0; off >>= 1) {
        p_in += __shfl_xor_sync(0xffffffffu, p_in, off);
        p0   += __shfl_xor_sync(0xffffffffu, p0, off);
        p1   += __shfl_xor_sync(0xffffffffu, p1, off);
        p2   += __shfl_xor_sync(0xffffffffu, p2, off);
    }

    const float alpha = __ldg(prelu);
    float sc0 = p_in + p0;
    float sc1 = p_in + p1;
    float sc2 = p_in + p2;
    sc0 = sc0 >= 0.f ? sc0 : alpha * sc0;
    sc1 = sc1 >= 0.f ? sc1 : alpha * sc1;
    sc2 = sc2 >= 0.f ? sc2 : alpha * sc2;

    const float m = fmaxf(sc0, fmaxf(sc1, sc2));
    const float e0 = __expf(sc0 - m);
    const float e1 = __expf(sc1 - m);
    const float e2 = __expf(sc2 - m);
    const float inv = 1.0f / (e0 + e1 + e2);

    if (lane < SS) {
        const float e = (lane == 0) ? e0 : (lane == 1 ? e1 : e2);
        out[((size_t)b * SS + lane) * AA + a] = e * inv;
    }
}

extern "C" void kernel_launch(void* const* d_in, const int* in_sizes, int n_in,
                              void* d_out, int out_size)
{
    const float* input     = (const float*)d_in[0];  // (B, A, D) f32
    const float* scattered = (const float*)d_in[1];  // (B, S, A, D) f32
    const float* weight    = (const float*)d_in[2];  // (2D,) f32
    const float* prelu     = (const float*)d_in[3];  // (1,) f32
    float* out = (float*)d_out;                      // (B, S, A) f32

    const int total_warps = BB * AA;                 // 262144
    const int threads = 256;                         // 8 warps / block
    const int blocks = total_warps / (threads / 32); // 32768
    spectral_attention_kernel<<<blocks, threads>>>(input, scattered, weight, prelu, out);
}